// round 14
// baseline (speedup 1.0000x reference)
#include <cuda_runtime.h>
#include <cuda_bf16.h>
#include <cuda_fp16.h>
#include <cstdint>

#define S_LEN  2048
#define BATCH  2
#define DMODEL 1024
#define NHEAD  16
#define DHEAD  64
#define MROWS  (BATCH * S_LEN)   // 4096

// Scratch (allocation-free rule: device globals). All fp16.
__device__ __half g_a16 [MROWS * DMODEL];        // activations single fp16 (x, then attn out)
__device__ __half g_wthi[4 * DMODEL * DMODEL];   // W^T hi: Wq,Wk,Wv,Wo
__device__ __half g_wtlo[4 * DMODEL * DMODEL];   // W^T lo
__device__ __half g_q16 [MROWS * DMODEL];        // Q single fp16, scaled 0.125*log2e
__device__ __half g_khi [MROWS * DMODEL];        // K 2-term split
__device__ __half g_klo [MROWS * DMODEL];
__device__ __half g_vhi [MROWS * DMODEL];        // V 2-term split
__device__ __half g_vlo [MROWS * DMODEL];

// ============================ helpers ======================================
__device__ __forceinline__ uint32_t smem_u32(const void* p) {
    uint32_t a;
    asm("{ .reg .u64 t; cvta.to.shared.u64 t, %1; cvt.u32.u64 %0, t; }" : "=r"(a) : "l"(p));
    return a;
}
__device__ __forceinline__ void ldm_x4(uint32_t* r, uint32_t addr) {
    asm volatile("ldmatrix.sync.aligned.m8n8.x4.shared.b16 {%0,%1,%2,%3}, [%4];"
                 : "=r"(r[0]), "=r"(r[1]), "=r"(r[2]), "=r"(r[3]) : "r"(addr));
}
__device__ __forceinline__ void ldm_x4t(uint32_t* r, uint32_t addr) {
    asm volatile("ldmatrix.sync.aligned.m8n8.x4.trans.shared.b16 {%0,%1,%2,%3}, [%4];"
                 : "=r"(r[0]), "=r"(r[1]), "=r"(r[2]), "=r"(r[3]) : "r"(addr));
}
__device__ __forceinline__ void mma_f16(float* c, const uint32_t* a, const uint32_t* b) {
    asm volatile("mma.sync.aligned.m16n8k16.row.col.f32.f16.f16.f32 "
                 "{%0,%1,%2,%3}, {%4,%5,%6,%7}, {%8,%9}, {%0,%1,%2,%3};"
                 : "+f"(c[0]), "+f"(c[1]), "+f"(c[2]), "+f"(c[3])
                 : "r"(a[0]), "r"(a[1]), "r"(a[2]), "r"(a[3]), "r"(b[0]), "r"(b[1]));
}
__device__ __forceinline__ float ex2(float x) {
    float y;
    asm("ex2.approx.f32 %0, %1;" : "=f"(y) : "f"(x));
    return y;
}
__device__ __forceinline__ uint32_t h2ex2(uint32_t x) {
    uint32_t y;
    asm("ex2.approx.f16x2 %0, %1;" : "=r"(y) : "r"(x));
    return y;
}
__device__ __forceinline__ void split_pack2_f16(float v0, float v1, uint32_t& hp, uint32_t& lp) {
    __half h0 = __float2half_rn(v0);
    __half h1 = __float2half_rn(v1);
    __half l0 = __float2half_rn(v0 - __half2float(h0));
    __half l1 = __float2half_rn(v1 - __half2float(h1));
    hp = (uint32_t)__half_as_ushort(h0) | ((uint32_t)__half_as_ushort(h1) << 16);
    lp = (uint32_t)__half_as_ushort(l0) | ((uint32_t)__half_as_ushort(l1) << 16);
}
__device__ __forceinline__ uint32_t cvt_f16x2(float v0, float v1) {
    uint32_t r;
    asm("cvt.rn.f16x2.f32 %0, %1, %2;" : "=r"(r) : "f"(v1), "f"(v0));
    return r;
}
__device__ __forceinline__ void cp_async16(uint32_t dst, const void* src) {
    asm volatile("cp.async.cg.shared.global [%0], [%1], 16;" :: "r"(dst), "l"(src));
}
#define CP_COMMIT() asm volatile("cp.async.commit_group;" ::: "memory")
#define CP_WAIT(N)  asm volatile("cp.async.wait_group %0;" :: "n"(N) : "memory")

#define LOG2E 1.4426950408889634f

// ===========================================================================
// Pre-convert kernels
// ===========================================================================
__global__ __launch_bounds__(256) void conv_single(
    const float* __restrict__ src, __half* __restrict__ dst, int n4)
{
    int i = blockIdx.x * blockDim.x + threadIdx.x;
    if (i >= n4) return;
    float4 v = ((const float4*)src)[i];
    uint2 o;
    o.x = cvt_f16x2(v.x, v.y);
    o.y = cvt_f16x2(v.z, v.w);
    ((uint2*)dst)[i] = o;
}

__global__ __launch_bounds__(256) void convT_split4(
    const float* __restrict__ W0, const float* __restrict__ W1,
    const float* __restrict__ W2, const float* __restrict__ W3,
    __half* __restrict__ hiB, __half* __restrict__ loB)
{
    __shared__ float t[32][33];
    const int z  = blockIdx.z;
    const float* W = (z == 0) ? W0 : (z == 1) ? W1 : (z == 2) ? W2 : W3;
    __half* hi = hiB + (size_t)z * DMODEL * DMODEL;
    __half* lo = loB + (size_t)z * DMODEL * DMODEL;
    const int bk = blockIdx.x * 32;
    const int bn = blockIdx.y * 32;
    const int tx = threadIdx.x, ty = threadIdx.y;
    #pragma unroll
    for (int j = 0; j < 4; j++)
        t[ty + 8 * j][tx] = W[(size_t)(bk + ty + 8 * j) * DMODEL + bn + tx];
    __syncthreads();
    #pragma unroll
    for (int j = 0; j < 4; j++) {
        float v = t[tx][ty + 8 * j];
        __half h = __float2half_rn(v);
        __half l = __float2half_rn(v - __half2float(h));
        size_t o = (size_t)(bn + ty + 8 * j) * DMODEL + bk + tx;
        hi[o] = h;
        lo[o] = l;
    }
}

// ===========================================================================
// cp.async 3-stage fp16 HMMA GEMM (single x split 2-term), ONE barrier per
// k-chunk. Per stage smem: A | Bhi | Blo (128x32 fp16, pitch 80B) = 30KB.
// ===========================================================================
#define GS_ARR   10240
#define GS_STAGE 30720
#define GS_TOTAL 92160            // 3 stages

__global__ __launch_bounds__(256, 2) void gemm_f16(
    const __half* __restrict__ A,
    const __half* __restrict__ Bhi, const __half* __restrict__ Blo,
    const float* __restrict__ bv0, const float* __restrict__ bv1, const float* __restrict__ bv2,
    float* __restrict__ C,
    __half* __restrict__ Q,
    __half* __restrict__ KH, __half* __restrict__ KL,
    __half* __restrict__ VH, __half* __restrict__ VL,
    int mode)
{
    extern __shared__ __align__(16) __half smb[];

    const int sel = blockIdx.x >> 3;
    const int n0  = (blockIdx.x & 7) * 128;
    const int m0  = blockIdx.y * 128;
    const __half* Bh = Bhi + ((size_t)sel << 20);
    const __half* Bl = Blo + ((size_t)sel << 20);
    const float* bias = (sel == 0) ? bv0 : (sel == 1) ? bv1 : bv2;

    const int tid  = threadIdx.x;
    const int wid  = tid >> 5;
    const int lane = tid & 31;
    const int wm = (wid >> 2) * 64;
    const int wn = (wid & 3) * 32;
    const uint32_t sb = smem_u32(smb);

    float acc[4][4][4] = {};

    auto load_stage = [&](int s, int ch) {
        const int kb = ch * 32;
        #pragma unroll
        for (int t = 0; t < 6; t++) {
            const int arr = t >> 1;                // 0=A, 1=Bhi, 2=Blo
            const int rem = tid + (t & 1) * 256;   // 0..511
            const int r = rem >> 2, c = rem & 3;
            uint32_t dst = sb + (uint32_t)(s * GS_STAGE + arr * GS_ARR + r * 80 + c * 16);
            const __half* g;
            if      (arr == 0) g = A  + (size_t)(m0 + r) * DMODEL + kb + c * 8;
            else if (arr == 1) g = Bh + (size_t)(n0 + r) * DMODEL + kb + c * 8;
            else               g = Bl + (size_t)(n0 + r) * DMODEL + kb + c * 8;
            cp_async16(dst, g);
        }
    };

    auto compute = [&](int s) {
        const uint32_t base = sb + s * GS_STAGE;
        #pragma unroll
        for (int ks = 0; ks < 2; ks++) {
            uint32_t bh[2][4], bl[2][4];
            #pragma unroll
            for (int np = 0; np < 2; np++) {
                uint32_t off = (uint32_t)((wn + np * 16 + (lane >> 4) * 8 + (lane & 7)) * 80
                                          + ((lane >> 3) & 1) * 16 + ks * 32);
                ldm_x4(bh[np], base + 1 * GS_ARR + off);
                ldm_x4(bl[np], base + 2 * GS_ARR + off);
            }
            #pragma unroll
            for (int mi = 0; mi < 4; mi++) {
                uint32_t a[4];
                uint32_t off = (uint32_t)((wm + mi * 16 + (lane & 15)) * 80
                                          + (ks * 16 + ((lane >> 4) & 1) * 8) * 2);
                ldm_x4(a, base + off);
                #pragma unroll
                for (int np = 0; np < 2; np++) {
                    mma_f16(acc[mi][2 * np],     a, &bh[np][0]);
                    mma_f16(acc[mi][2 * np],     a, &bl[np][0]);
                    mma_f16(acc[mi][2 * np + 1], a, &bh[np][2]);
                    mma_f16(acc[mi][2 * np + 1], a, &bl[np][2]);
                }
            }
        }
    };

    load_stage(0, 0);
    CP_COMMIT();
    for (int ch = 0; ch < 32; ch++) {
        if (ch < 31) load_stage((ch + 1) % 3, ch + 1);
        CP_COMMIT();
        CP_WAIT(1);
        __syncthreads();
        compute(ch % 3);
    }

    const int qrow = lane >> 2;
    const int qcol = (lane & 3) * 2;

    if (mode == 0) {
        #pragma unroll
        for (int mi = 0; mi < 4; mi++) {
            #pragma unroll
            for (int ni = 0; ni < 4; ni++) {
                int col = n0 + wn + ni * 8 + qcol;
                float2 bb = *(const float2*)&bias[col];
                int r0 = m0 + wm + mi * 16 + qrow;
                *(float2*)&C[(size_t)r0 * DMODEL + col] =
                    make_float2(acc[mi][ni][0] + bb.x, acc[mi][ni][1] + bb.y);
                *(float2*)&C[(size_t)(r0 + 8) * DMODEL + col] =
                    make_float2(acc[mi][ni][2] + bb.x, acc[mi][ni][3] + bb.y);
            }
        }
    } else if (sel == 0) {
        const float scl = 0.125f * LOG2E;
        #pragma unroll
        for (int mi = 0; mi < 4; mi++) {
            #pragma unroll
            for (int ni = 0; ni < 4; ni++) {
                int col = n0 + wn + ni * 8 + qcol;
                float2 bb = *(const float2*)&bias[col];
                int r0 = m0 + wm + mi * 16 + qrow;
                *(uint32_t*)&Q[(size_t)r0 * DMODEL + col] =
                    cvt_f16x2((acc[mi][ni][0] + bb.x) * scl, (acc[mi][ni][1] + bb.y) * scl);
                *(uint32_t*)&Q[(size_t)(r0 + 8) * DMODEL + col] =
                    cvt_f16x2((acc[mi][ni][2] + bb.x) * scl, (acc[mi][ni][3] + bb.y) * scl);
            }
        }
    } else {
        __half* H = (sel == 1) ? KH : VH;
        __half* L = (sel == 1) ? KL : VL;
        #pragma unroll
        for (int mi = 0; mi < 4; mi++) {
            #pragma unroll
            for (int ni = 0; ni < 4; ni++) {
                int col = n0 + wn + ni * 8 + qcol;
                float2 bb = *(const float2*)&bias[col];
                int r0 = m0 + wm + mi * 16 + qrow;
                uint32_t hp, lp;
                split_pack2_f16(acc[mi][ni][0] + bb.x, acc[mi][ni][1] + bb.y, hp, lp);
                *(uint32_t*)&H[(size_t)r0 * DMODEL + col] = hp;
                *(uint32_t*)&L[(size_t)r0 * DMODEL + col] = lp;
                split_pack2_f16(acc[mi][ni][2] + bb.x, acc[mi][ni][3] + bb.y, hp, lp);
                *(uint32_t*)&H[(size_t)(r0 + 8) * DMODEL + col] = hp;
                *(uint32_t*)&L[(size_t)(r0 + 8) * DMODEL + col] = lp;
            }
        }
    }
}

// ===========================================================================
// fp16 HMMA flash attention (causal), deferred-PV overlap:
// iteration kt runs scores(kt) and PV(kt-1) (independent MMA groups), so the
// softmax serial chain of tile kt co-issues with PV(kt-1)'s tensor work.
// Rescale ordering is mathematically identical: o += P(kt-1)V (frame kt-1),
// then o *= a(kt). Loads issued AFTER the barrier (stage (kt+1)%3's V is
// read at iter kt-1 via the PV lag). Epilogue flushes PV(nkt-1) if computed.
// ===========================================================================
#define AT_PITCHB 144            // 72 halfs * 2B per row (64 data + 8 pad)
#define AT_KARR   9216           // 64*144
#define AT_STAGE  36864          // Khi|Klo|Vhi|Vlo
#define AT_SMEM   (3*AT_STAGE)   // 110592

__global__ __launch_bounds__(256, 2) void attn_mma(
    const __half* __restrict__ Q16,
    const __half* __restrict__ Khi, const __half* __restrict__ Klo,
    const __half* __restrict__ Vhi, const __half* __restrict__ Vlo,
    __half* __restrict__ OF)
{
    extern __shared__ __align__(16) char sma[];
    const uint32_t sb = smem_u32(sma);

    const int qq = (int)(gridDim.x - 1) - (int)blockIdx.x;  // longest first
    const int h  = blockIdx.y;
    const int b  = blockIdx.z;
    const int tid  = threadIdx.x;
    const int wid  = tid >> 5;
    const int lane = tid & 31;
    const int wm = wid * 16;
    const int colh = h * DHEAD;
    const int qrow0 = b * S_LEN + qq * 128;
    const int rowlim = qq * 128 + wm + 15;      // causal reach of this warp

    // ---- prologue A: stream Q (single) into stage-0 region via cp.async ----
    #pragma unroll
    for (int t = 0; t < 4; t++) {
        const int rem = tid + t * 256;
        const int r = rem >> 3, c = rem & 7;
        uint32_t dst = sb + (uint32_t)(r * AT_PITCHB + c * 16);
        cp_async16(dst, Q16 + (size_t)(qrow0 + r) * DMODEL + colh + c * 8);
    }
    CP_COMMIT();
    CP_WAIT(0);
    __syncthreads();

    // ---- prologue B: Q fragments -> registers ----
    uint32_t qr[4][4];
    #pragma unroll
    for (int ks = 0; ks < 4; ks++) {
        uint32_t qoff = (uint32_t)((wm + (lane & 15)) * AT_PITCHB
                                   + ((lane >> 4) & 1) * 16 + ks * 32);
        ldm_x4(qr[ks], sb + qoff);
    }
    __syncthreads();   // Q reads complete before stage-0 K/V overwrite

    const uint32_t vone[2] = { 0x3C003C00u, 0x3C003C00u };

    auto load_stage = [&](int s, int kt) {
        const int key0 = kt * 64;
        #pragma unroll
        for (int t = 0; t < 8; t++) {
            const int arr = t >> 1;
            const int rem = tid + (t & 1) * 256;
            const int r = rem >> 3, c = rem & 7;
            uint32_t dst = sb + s * AT_STAGE + arr * AT_KARR
                         + (uint32_t)(r * AT_PITCHB + c * 16);
            const __half* g;
            if      (arr == 0) g = Khi + (size_t)(b * S_LEN + key0 + r) * DMODEL + colh + c * 8;
            else if (arr == 1) g = Klo + (size_t)(b * S_LEN + key0 + r) * DMODEL + colh + c * 8;
            else if (arr == 2) g = Vhi + (size_t)(b * S_LEN + key0 + r) * DMODEL + colh + c * 8;
            else               g = Vlo + (size_t)(b * S_LEN + key0 + r) * DMODEL + colh + c * 8;
            cp_async16(dst, g);
        }
    };

    // PV of a stored P fragment set against V in stage `stv`.
    float o[8][4] = {};
    float ol[4] = {};
    uint32_t P01[8], P23[8];          // P fragments of the PREVIOUS tile
    float m0 = -1e30f, m1 = -1e30f;

    auto pv_tile = [&](uint32_t stv) {
        #pragma unroll
        for (int ks = 0; ks < 4; ks++) {
            uint32_t ph[4];
            ph[0] = P01[2 * ks];
            ph[1] = P23[2 * ks];
            ph[2] = P01[2 * ks + 1];
            ph[3] = P23[2 * ks + 1];
            #pragma unroll
            for (int np = 0; np < 4; np++) {
                uint32_t vh[4], vl[4];
                uint32_t voff = (uint32_t)((ks * 16 + ((lane >> 3) & 1) * 8 + (lane & 7)) * AT_PITCHB
                                           + np * 32 + (lane >> 4) * 16);
                ldm_x4t(vh, stv + 2 * AT_KARR + voff);
                ldm_x4t(vl, stv + 3 * AT_KARR + voff);
                mma_f16(o[2 * np],     ph, &vh[0]);
                mma_f16(o[2 * np],     ph, &vl[0]);
                mma_f16(o[2 * np + 1], ph, &vh[2]);
                mma_f16(o[2 * np + 1], ph, &vl[2]);
            }
            mma_f16(ol, ph, vone);
        }
    };

    const int nkt = 2 * qq + 2;
    load_stage(0, 0);
    CP_COMMIT();

    for (int kt = 0; kt < nkt; kt++) {
        CP_WAIT(0);                   // stage kt data resident
        __syncthreads();              // + all of iter kt-1's compute done
        if (kt + 1 < nkt) { load_stage((kt + 1) % 3, kt + 1); CP_COMMIT(); }

        const bool cur = (kt * 64 <= rowlim);
        float sv[8][4] = {};

        if (cur) {
            const uint32_t st = sb + (kt % 3) * AT_STAGE;
            // ---- S = Q K^T (2-term; Q from registers) ----
            #pragma unroll
            for (int ks = 0; ks < 4; ks++) {
                #pragma unroll
                for (int np = 0; np < 4; np++) {
                    uint32_t kh[4], kl[4];
                    uint32_t koff = (uint32_t)((np * 16 + (lane >> 4) * 8 + (lane & 7)) * AT_PITCHB
                                               + ((lane >> 3) & 1) * 16 + ks * 32);
                    ldm_x4(kh, st + koff);
                    ldm_x4(kl, st + AT_KARR + koff);
                    mma_f16(sv[2 * np],     qr[ks], &kh[0]);
                    mma_f16(sv[2 * np],     qr[ks], &kl[0]);
                    mma_f16(sv[2 * np + 1], qr[ks], &kh[2]);
                    mma_f16(sv[2 * np + 1], qr[ks], &kl[2]);
                }
            }
            // ---- causal mask ----
            if (kt * 64 + 63 > qq * 128) {
                const int rg0 = qq * 128 + wm + (lane >> 2);
                const int cg  = kt * 64 + (lane & 3) * 2;
                #pragma unroll
                for (int n = 0; n < 8; n++) {
                    int c0 = cg + n * 8, c1 = c0 + 1;
                    if (c0 > rg0)     sv[n][0] = -1e10f;
                    if (c1 > rg0)     sv[n][1] = -1e10f;
                    if (c0 > rg0 + 8) sv[n][2] = -1e10f;
                    if (c1 > rg0 + 8) sv[n][3] = -1e10f;
                }
            }
        }

        // ---- PV of PREVIOUS tile (independent of the softmax chain above;
        //      co-issues with the shuffle/ex2 section below) ----
        if (kt >= 1) pv_tile(sb + ((kt - 1) % 3) * AT_STAGE);

        if (cur) {
            // ---- online max update (quad shuffles) ----
            float rm0 = -1e30f, rm1 = -1e30f;
            #pragma unroll
            for (int n = 0; n < 8; n++) {
                rm0 = fmaxf(rm0, fmaxf(sv[n][0], sv[n][1]));
                rm1 = fmaxf(rm1, fmaxf(sv[n][2], sv[n][3]));
            }
            rm0 = fmaxf(rm0, __shfl_xor_sync(0xffffffffu, rm0, 1));
            rm0 = fmaxf(rm0, __shfl_xor_sync(0xffffffffu, rm0, 2));
            rm1 = fmaxf(rm1, __shfl_xor_sync(0xffffffffu, rm1, 1));
            rm1 = fmaxf(rm1, __shfl_xor_sync(0xffffffffu, rm1, 2));
            float mn0 = fmaxf(m0, rm0), mn1 = fmaxf(m1, rm1);
            float a0 = ex2(m0 - mn0), a1 = ex2(m1 - mn1);
            m0 = mn0; m1 = mn1;

            // rescale AFTER PV(kt-1) was added (o still in frame kt-1 above)
            #pragma unroll
            for (int n = 0; n < 8; n++) {
                P01[n] = h2ex2(cvt_f16x2(sv[n][0] - mn0, sv[n][1] - mn0));
                P23[n] = h2ex2(cvt_f16x2(sv[n][2] - mn1, sv[n][3] - mn1));
                o[n][0] *= a0; o[n][1] *= a0;
                o[n][2] *= a1; o[n][3] *= a1;
            }
            ol[0] *= a0; ol[1] *= a0; ol[2] *= a1; ol[3] *= a1;
        }
    }

    // ---- epilogue flush: PV of the final tile, if this warp computed it ----
    if ((nkt - 1) * 64 <= rowlim)
        pv_tile(sb + ((nkt - 1) % 3) * AT_STAGE);

    // ---- finalize: divide by l, store single fp16 ----
    const float inv0 = 1.0f / ol[0];
    const float inv1 = 1.0f / ol[2];
    const int r0 = qrow0 + wm + (lane >> 2);
    const int qc = (lane & 3) * 2;
    #pragma unroll
    for (int n = 0; n < 8; n++) {
        int col = colh + n * 8 + qc;
        *(uint32_t*)&OF[(size_t)r0 * DMODEL + col] =
            cvt_f16x2(o[n][0] * inv0, o[n][1] * inv0);
        *(uint32_t*)&OF[(size_t)(r0 + 8) * DMODEL + col] =
            cvt_f16x2(o[n][2] * inv1, o[n][3] * inv1);
    }
}

// ---------------------------------------------------------------------------
extern "C" void kernel_launch(void* const* d_in, const int* in_sizes, int n_in,
                              void* d_out, int out_size)
{
    const float* x  = (const float*)d_in[0];
    const float* Wq = (const float*)d_in[1];
    const float* bq = (const float*)d_in[2];
    const float* Wk = (const float*)d_in[3];
    const float* bk = (const float*)d_in[4];
    const float* Wv = (const float*)d_in[5];
    const float* bv = (const float*)d_in[6];
    const float* Wo = (const float*)d_in[7];
    const float* bo = (const float*)d_in[8];
    float* out = (float*)d_out;

    __half *a16, *wthi, *wtlo, *q16, *khi, *klo, *vhi, *vlo;
    cudaGetSymbolAddress((void**)&a16, g_a16);
    cudaGetSymbolAddress((void**)&wthi, g_wthi);
    cudaGetSymbolAddress((void**)&wtlo, g_wtlo);
    cudaGetSymbolAddress((void**)&q16, g_q16);
    cudaGetSymbolAddress((void**)&khi, g_khi);
    cudaGetSymbolAddress((void**)&klo, g_klo);
    cudaGetSymbolAddress((void**)&vhi, g_vhi);
    cudaGetSymbolAddress((void**)&vlo, g_vlo);

    cudaFuncSetAttribute(gemm_f16, cudaFuncAttributeMaxDynamicSharedMemorySize, GS_TOTAL);
    cudaFuncSetAttribute(attn_mma, cudaFuncAttributeMaxDynamicSharedMemorySize, AT_SMEM);

    const int WSZ = DMODEL * DMODEL;
    const int N4  = MROWS * DMODEL / 4;

    // 1) x -> single fp16; transpose + fp16-split all 4 weights
    conv_single<<<(N4 + 255) / 256, 256>>>(x, a16, N4);
    convT_split4<<<dim3(32, 32, 4), dim3(32, 8)>>>(Wq, Wk, Wv, Wo, wthi, wtlo);

    // 2) fused QKV projection: Q single (scaled), K/V split fp16
    gemm_f16<<<dim3(24, 32), 256, GS_TOTAL>>>(
        a16, wthi, wtlo, bq, bk, bv,
        nullptr, q16, khi, klo, vhi, vlo, 1);

    // 3) fp16 attention -> single fp16 output into a16
    attn_mma<<<dim3(S_LEN / 128, NHEAD, BATCH), 256, AT_SMEM>>>(
        q16, khi, klo, vhi, vlo, a16);

    // 4) output projection -> fp32 final
    gemm_f16<<<dim3(8, 32), 256, GS_TOTAL>>>(
        a16, wthi + 3 * WSZ, wtlo + 3 * WSZ, bo, bo, bo,
        out, nullptr, nullptr, nullptr, nullptr, nullptr, 0);
}

// round 15
// speedup vs baseline: 1.0378x; 1.0378x over previous
#include <cuda_runtime.h>
#include <cuda_bf16.h>
#include <cuda_fp16.h>
#include <cstdint>

#define S_LEN  2048
#define BATCH  2
#define DMODEL 1024
#define NHEAD  16
#define DHEAD  64
#define MROWS  (BATCH * S_LEN)   // 4096

// Scratch (allocation-free rule: device globals). All fp16.
__device__ __half g_a16 [MROWS * DMODEL];        // activations single fp16 (x, then attn out)
__device__ __half g_wthi[4 * DMODEL * DMODEL];   // W^T hi: Wq,Wk,Wv,Wo
__device__ __half g_wtlo[4 * DMODEL * DMODEL];   // W^T lo
__device__ __half g_q16 [MROWS * DMODEL];        // Q single fp16, scaled 0.125*log2e
__device__ __half g_khi [MROWS * DMODEL];        // K 2-term split
__device__ __half g_klo [MROWS * DMODEL];
__device__ __half g_vhi [MROWS * DMODEL];        // V 2-term split
__device__ __half g_vlo [MROWS * DMODEL];

// ============================ helpers ======================================
__device__ __forceinline__ uint32_t smem_u32(const void* p) {
    uint32_t a;
    asm("{ .reg .u64 t; cvta.to.shared.u64 t, %1; cvt.u32.u64 %0, t; }" : "=r"(a) : "l"(p));
    return a;
}
__device__ __forceinline__ void ldm_x4(uint32_t* r, uint32_t addr) {
    asm volatile("ldmatrix.sync.aligned.m8n8.x4.shared.b16 {%0,%1,%2,%3}, [%4];"
                 : "=r"(r[0]), "=r"(r[1]), "=r"(r[2]), "=r"(r[3]) : "r"(addr));
}
__device__ __forceinline__ void ldm_x4t(uint32_t* r, uint32_t addr) {
    asm volatile("ldmatrix.sync.aligned.m8n8.x4.trans.shared.b16 {%0,%1,%2,%3}, [%4];"
                 : "=r"(r[0]), "=r"(r[1]), "=r"(r[2]), "=r"(r[3]) : "r"(addr));
}
__device__ __forceinline__ void mma_f16(float* c, const uint32_t* a, const uint32_t* b) {
    asm volatile("mma.sync.aligned.m16n8k16.row.col.f32.f16.f16.f32 "
                 "{%0,%1,%2,%3}, {%4,%5,%6,%7}, {%8,%9}, {%0,%1,%2,%3};"
                 : "+f"(c[0]), "+f"(c[1]), "+f"(c[2]), "+f"(c[3])
                 : "r"(a[0]), "r"(a[1]), "r"(a[2]), "r"(a[3]), "r"(b[0]), "r"(b[1]));
}
__device__ __forceinline__ float ex2(float x) {
    float y;
    asm("ex2.approx.f32 %0, %1;" : "=f"(y) : "f"(x));
    return y;
}
__device__ __forceinline__ uint32_t h2ex2(uint32_t x) {
    uint32_t y;
    asm("ex2.approx.f16x2 %0, %1;" : "=r"(y) : "r"(x));
    return y;
}
__device__ __forceinline__ void split_pack2_f16(float v0, float v1, uint32_t& hp, uint32_t& lp) {
    __half h0 = __float2half_rn(v0);
    __half h1 = __float2half_rn(v1);
    __half l0 = __float2half_rn(v0 - __half2float(h0));
    __half l1 = __float2half_rn(v1 - __half2float(h1));
    hp = (uint32_t)__half_as_ushort(h0) | ((uint32_t)__half_as_ushort(h1) << 16);
    lp = (uint32_t)__half_as_ushort(l0) | ((uint32_t)__half_as_ushort(l1) << 16);
}
__device__ __forceinline__ uint32_t cvt_f16x2(float v0, float v1) {
    uint32_t r;
    asm("cvt.rn.f16x2.f32 %0, %1, %2;" : "=r"(r) : "f"(v1), "f"(v0));
    return r;
}
__device__ __forceinline__ void cp_async16(uint32_t dst, const void* src) {
    asm volatile("cp.async.cg.shared.global [%0], [%1], 16;" :: "r"(dst), "l"(src));
}
#define CP_COMMIT() asm volatile("cp.async.commit_group;" ::: "memory")
#define CP_WAIT(N)  asm volatile("cp.async.wait_group %0;" :: "n"(N) : "memory")

#define LOG2E 1.4426950408889634f

// ===========================================================================
// Merged pre-convert: blockIdx.z < 4 -> transpose+split weight z;
//                     blockIdx.z == 4 -> x -> single fp16 (grid-stride).
// ===========================================================================
__global__ __launch_bounds__(256) void conv_all(
    const float* __restrict__ X,
    const float* __restrict__ W0, const float* __restrict__ W1,
    const float* __restrict__ W2, const float* __restrict__ W3,
    __half* __restrict__ a16,
    __half* __restrict__ hiB, __half* __restrict__ loB)
{
    const int z = blockIdx.z;
    if (z == 4) {
        // x -> single fp16: 1M float4 over 1024 blocks x 256 thr, 4 per thread
        const int n4 = MROWS * DMODEL / 4;
        int base = (blockIdx.y * gridDim.x + blockIdx.x) * 256 + threadIdx.x;
        const int stride = gridDim.x * gridDim.y * 256;
        for (int i = base; i < n4; i += stride) {
            float4 v = ((const float4*)X)[i];
            uint2 o;
            o.x = cvt_f16x2(v.x, v.y);
            o.y = cvt_f16x2(v.z, v.w);
            ((uint2*)a16)[i] = o;
        }
        return;
    }

    __shared__ float t[32][33];
    const float* W = (z == 0) ? W0 : (z == 1) ? W1 : (z == 2) ? W2 : W3;
    __half* hi = hiB + (size_t)z * DMODEL * DMODEL;
    __half* lo = loB + (size_t)z * DMODEL * DMODEL;
    const int bk = blockIdx.x * 32;
    const int bn = blockIdx.y * 32;
    const int tx = threadIdx.x & 31;
    const int ty = threadIdx.x >> 5;   // 0..7
    #pragma unroll
    for (int j = 0; j < 4; j++)
        t[ty + 8 * j][tx] = W[(size_t)(bk + ty + 8 * j) * DMODEL + bn + tx];
    __syncthreads();
    #pragma unroll
    for (int j = 0; j < 4; j++) {
        float v = t[tx][ty + 8 * j];
        __half h = __float2half_rn(v);
        __half l = __float2half_rn(v - __half2float(h));
        size_t o = (size_t)(bn + ty + 8 * j) * DMODEL + bk + tx;
        hi[o] = h;
        lo[o] = l;
    }
}

// ===========================================================================
// cp.async 3-stage fp16 HMMA GEMM (single x split 2-term), ONE barrier per
// k-chunk. Per stage smem: A | Bhi | Blo (128x32 fp16, pitch 80B) = 30KB.
// ===========================================================================
#define GS_ARR   10240
#define GS_STAGE 30720
#define GS_TOTAL 92160            // 3 stages

__global__ __launch_bounds__(256, 2) void gemm_f16(
    const __half* __restrict__ A,
    const __half* __restrict__ Bhi, const __half* __restrict__ Blo,
    const float* __restrict__ bv0, const float* __restrict__ bv1, const float* __restrict__ bv2,
    float* __restrict__ C,
    __half* __restrict__ Q,
    __half* __restrict__ KH, __half* __restrict__ KL,
    __half* __restrict__ VH, __half* __restrict__ VL,
    int mode)
{
    extern __shared__ __align__(16) __half smb[];

    const int sel = blockIdx.x >> 3;
    const int n0  = (blockIdx.x & 7) * 128;
    const int m0  = blockIdx.y * 128;
    const __half* Bh = Bhi + ((size_t)sel << 20);
    const __half* Bl = Blo + ((size_t)sel << 20);
    const float* bias = (sel == 0) ? bv0 : (sel == 1) ? bv1 : bv2;

    const int tid  = threadIdx.x;
    const int wid  = tid >> 5;
    const int lane = tid & 31;
    const int wm = (wid >> 2) * 64;
    const int wn = (wid & 3) * 32;
    const uint32_t sb = smem_u32(smb);

    float acc[4][4][4] = {};

    auto load_stage = [&](int s, int ch) {
        const int kb = ch * 32;
        #pragma unroll
        for (int t = 0; t < 6; t++) {
            const int arr = t >> 1;                // 0=A, 1=Bhi, 2=Blo
            const int rem = tid + (t & 1) * 256;   // 0..511
            const int r = rem >> 2, c = rem & 3;
            uint32_t dst = sb + (uint32_t)(s * GS_STAGE + arr * GS_ARR + r * 80 + c * 16);
            const __half* g;
            if      (arr == 0) g = A  + (size_t)(m0 + r) * DMODEL + kb + c * 8;
            else if (arr == 1) g = Bh + (size_t)(n0 + r) * DMODEL + kb + c * 8;
            else               g = Bl + (size_t)(n0 + r) * DMODEL + kb + c * 8;
            cp_async16(dst, g);
        }
    };

    auto compute = [&](int s) {
        const uint32_t base = sb + s * GS_STAGE;
        #pragma unroll
        for (int ks = 0; ks < 2; ks++) {
            uint32_t bh[2][4], bl[2][4];
            #pragma unroll
            for (int np = 0; np < 2; np++) {
                uint32_t off = (uint32_t)((wn + np * 16 + (lane >> 4) * 8 + (lane & 7)) * 80
                                          + ((lane >> 3) & 1) * 16 + ks * 32);
                ldm_x4(bh[np], base + 1 * GS_ARR + off);
                ldm_x4(bl[np], base + 2 * GS_ARR + off);
            }
            #pragma unroll
            for (int mi = 0; mi < 4; mi++) {
                uint32_t a[4];
                uint32_t off = (uint32_t)((wm + mi * 16 + (lane & 15)) * 80
                                          + (ks * 16 + ((lane >> 4) & 1) * 8) * 2);
                ldm_x4(a, base + off);
                #pragma unroll
                for (int np = 0; np < 2; np++) {
                    mma_f16(acc[mi][2 * np],     a, &bh[np][0]);
                    mma_f16(acc[mi][2 * np],     a, &bl[np][0]);
                    mma_f16(acc[mi][2 * np + 1], a, &bh[np][2]);
                    mma_f16(acc[mi][2 * np + 1], a, &bl[np][2]);
                }
            }
        }
    };

    load_stage(0, 0);
    CP_COMMIT();
    for (int ch = 0; ch < 32; ch++) {
        if (ch < 31) load_stage((ch + 1) % 3, ch + 1);
        CP_COMMIT();
        CP_WAIT(1);
        __syncthreads();
        compute(ch % 3);
    }

    const int qrow = lane >> 2;
    const int qcol = (lane & 3) * 2;

    if (mode == 0) {
        #pragma unroll
        for (int mi = 0; mi < 4; mi++) {
            #pragma unroll
            for (int ni = 0; ni < 4; ni++) {
                int col = n0 + wn + ni * 8 + qcol;
                float2 bb = *(const float2*)&bias[col];
                int r0 = m0 + wm + mi * 16 + qrow;
                *(float2*)&C[(size_t)r0 * DMODEL + col] =
                    make_float2(acc[mi][ni][0] + bb.x, acc[mi][ni][1] + bb.y);
                *(float2*)&C[(size_t)(r0 + 8) * DMODEL + col] =
                    make_float2(acc[mi][ni][2] + bb.x, acc[mi][ni][3] + bb.y);
            }
        }
    } else if (sel == 0) {
        const float scl = 0.125f * LOG2E;
        #pragma unroll
        for (int mi = 0; mi < 4; mi++) {
            #pragma unroll
            for (int ni = 0; ni < 4; ni++) {
                int col = n0 + wn + ni * 8 + qcol;
                float2 bb = *(const float2*)&bias[col];
                int r0 = m0 + wm + mi * 16 + qrow;
                *(uint32_t*)&Q[(size_t)r0 * DMODEL + col] =
                    cvt_f16x2((acc[mi][ni][0] + bb.x) * scl, (acc[mi][ni][1] + bb.y) * scl);
                *(uint32_t*)&Q[(size_t)(r0 + 8) * DMODEL + col] =
                    cvt_f16x2((acc[mi][ni][2] + bb.x) * scl, (acc[mi][ni][3] + bb.y) * scl);
            }
        }
    } else {
        __half* H = (sel == 1) ? KH : VH;
        __half* L = (sel == 1) ? KL : VL;
        #pragma unroll
        for (int mi = 0; mi < 4; mi++) {
            #pragma unroll
            for (int ni = 0; ni < 4; ni++) {
                int col = n0 + wn + ni * 8 + qcol;
                float2 bb = *(const float2*)&bias[col];
                int r0 = m0 + wm + mi * 16 + qrow;
                uint32_t hp, lp;
                split_pack2_f16(acc[mi][ni][0] + bb.x, acc[mi][ni][1] + bb.y, hp, lp);
                *(uint32_t*)&H[(size_t)r0 * DMODEL + col] = hp;
                *(uint32_t*)&L[(size_t)r0 * DMODEL + col] = lp;
                split_pack2_f16(acc[mi][ni][2] + bb.x, acc[mi][ni][3] + bb.y, hp, lp);
                *(uint32_t*)&H[(size_t)(r0 + 8) * DMODEL + col] = hp;
                *(uint32_t*)&L[(size_t)(r0 + 8) * DMODEL + col] = lp;
            }
        }
    }
}

// ===========================================================================
// fp16 HMMA flash attention (causal), exp2 softmax with ex2.approx.f16x2 —
// exact R13 structure (proven 132us / rel_err 5.1e-4).
// ===========================================================================
#define AT_PITCHB 144            // 72 halfs * 2B per row (64 data + 8 pad)
#define AT_KARR   9216           // 64*144
#define AT_STAGE  36864          // Khi|Klo|Vhi|Vlo
#define AT_SMEM   (3*AT_STAGE)   // 110592

__global__ __launch_bounds__(256, 2) void attn_mma(
    const __half* __restrict__ Q16,
    const __half* __restrict__ Khi, const __half* __restrict__ Klo,
    const __half* __restrict__ Vhi, const __half* __restrict__ Vlo,
    __half* __restrict__ OF)
{
    extern __shared__ __align__(16) char sma[];
    const uint32_t sb = smem_u32(sma);

    const int qq = (int)(gridDim.x - 1) - (int)blockIdx.x;  // longest first
    const int h  = blockIdx.y;
    const int b  = blockIdx.z;
    const int tid  = threadIdx.x;
    const int wid  = tid >> 5;
    const int lane = tid & 31;
    const int wm = wid * 16;
    const int colh = h * DHEAD;
    const int qrow0 = b * S_LEN + qq * 128;

    // ---- prologue A: stream Q (single) into stage-0 region via cp.async ----
    #pragma unroll
    for (int t = 0; t < 4; t++) {
        const int rem = tid + t * 256;
        const int r = rem >> 3, c = rem & 7;
        uint32_t dst = sb + (uint32_t)(r * AT_PITCHB + c * 16);
        cp_async16(dst, Q16 + (size_t)(qrow0 + r) * DMODEL + colh + c * 8);
    }
    CP_COMMIT();
    CP_WAIT(0);
    __syncthreads();

    // ---- prologue B: Q fragments -> registers ----
    uint32_t qr[4][4];
    #pragma unroll
    for (int ks = 0; ks < 4; ks++) {
        uint32_t qoff = (uint32_t)((wm + (lane & 15)) * AT_PITCHB
                                   + ((lane >> 4) & 1) * 16 + ks * 32);
        ldm_x4(qr[ks], sb + qoff);
    }
    __syncthreads();   // Q reads complete before stage-0 K/V overwrite

    const uint32_t vone[2] = { 0x3C003C00u, 0x3C003C00u };

    auto load_stage = [&](int s, int kt) {
        const int key0 = kt * 64;
        #pragma unroll
        for (int t = 0; t < 8; t++) {
            const int arr = t >> 1;
            const int rem = tid + (t & 1) * 256;
            const int r = rem >> 3, c = rem & 7;
            uint32_t dst = sb + s * AT_STAGE + arr * AT_KARR
                         + (uint32_t)(r * AT_PITCHB + c * 16);
            const __half* g;
            if      (arr == 0) g = Khi + (size_t)(b * S_LEN + key0 + r) * DMODEL + colh + c * 8;
            else if (arr == 1) g = Klo + (size_t)(b * S_LEN + key0 + r) * DMODEL + colh + c * 8;
            else if (arr == 2) g = Vhi + (size_t)(b * S_LEN + key0 + r) * DMODEL + colh + c * 8;
            else               g = Vlo + (size_t)(b * S_LEN + key0 + r) * DMODEL + colh + c * 8;
            cp_async16(dst, g);
        }
    };

    const int nkt = 2 * qq + 2;
    load_stage(0, 0);
    CP_COMMIT();

    float o[8][4] = {};
    float ol[4] = {};                 // ones-fragment accumulator (l carrier)
    float m0 = -1e30f, m1 = -1e30f;

    for (int kt = 0; kt < nkt; kt++) {
        if (kt + 1 < nkt) load_stage((kt + 1) % 3, kt + 1);
        CP_COMMIT();
        CP_WAIT(1);
        __syncthreads();              // ONE barrier per key tile

        if (kt * 64 <= qq * 128 + wm + 15) {
            const uint32_t st = sb + (kt % 3) * AT_STAGE;

            // ---- S = Q K^T (2-term: q*kh + q*kl; Q from registers) ----
            float sv[8][4] = {};
            #pragma unroll
            for (int ks = 0; ks < 4; ks++) {
                #pragma unroll
                for (int np = 0; np < 4; np++) {
                    uint32_t kh[4], kl[4];
                    uint32_t koff = (uint32_t)((np * 16 + (lane >> 4) * 8 + (lane & 7)) * AT_PITCHB
                                               + ((lane >> 3) & 1) * 16 + ks * 32);
                    ldm_x4(kh, st + koff);
                    ldm_x4(kl, st + AT_KARR + koff);
                    mma_f16(sv[2 * np],     qr[ks], &kh[0]);
                    mma_f16(sv[2 * np],     qr[ks], &kl[0]);
                    mma_f16(sv[2 * np + 1], qr[ks], &kh[2]);
                    mma_f16(sv[2 * np + 1], qr[ks], &kl[2]);
                }
            }

            // ---- causal mask ----
            if (kt * 64 + 63 > qq * 128) {
                const int rg0 = qq * 128 + wm + (lane >> 2);
                const int cg  = kt * 64 + (lane & 3) * 2;
                #pragma unroll
                for (int n = 0; n < 8; n++) {
                    int c0 = cg + n * 8, c1 = c0 + 1;
                    if (c0 > rg0)     sv[n][0] = -1e10f;
                    if (c1 > rg0)     sv[n][1] = -1e10f;
                    if (c0 > rg0 + 8) sv[n][2] = -1e10f;
                    if (c1 > rg0 + 8) sv[n][3] = -1e10f;
                }
            }

            // ---- online max update (quad shuffles) ----
            float rm0 = -1e30f, rm1 = -1e30f;
            #pragma unroll
            for (int n = 0; n < 8; n++) {
                rm0 = fmaxf(rm0, fmaxf(sv[n][0], sv[n][1]));
                rm1 = fmaxf(rm1, fmaxf(sv[n][2], sv[n][3]));
            }
            rm0 = fmaxf(rm0, __shfl_xor_sync(0xffffffffu, rm0, 1));
            rm0 = fmaxf(rm0, __shfl_xor_sync(0xffffffffu, rm0, 2));
            rm1 = fmaxf(rm1, __shfl_xor_sync(0xffffffffu, rm1, 1));
            rm1 = fmaxf(rm1, __shfl_xor_sync(0xffffffffu, rm1, 2));
            float mn0 = fmaxf(m0, rm0), mn1 = fmaxf(m1, rm1);
            float a0 = ex2(m0 - mn0), a1 = ex2(m1 - mn1);
            m0 = mn0; m1 = mn1;

            // ---- P = exp2(S - m): fp32 diff -> f16x2 pack -> ex2.f16x2 ----
            uint32_t p01[8], p23[8];
            #pragma unroll
            for (int n = 0; n < 8; n++) {
                p01[n] = h2ex2(cvt_f16x2(sv[n][0] - mn0, sv[n][1] - mn0));
                p23[n] = h2ex2(cvt_f16x2(sv[n][2] - mn1, sv[n][3] - mn1));
                o[n][0] *= a0; o[n][1] *= a0;
                o[n][2] *= a1; o[n][3] *= a1;
            }
            ol[0] *= a0; ol[1] *= a0; ol[2] *= a1; ol[3] *= a1;

            // ---- O += P V; l += P @ ones (constant fragment) ----
            #pragma unroll
            for (int ks = 0; ks < 4; ks++) {
                uint32_t ph[4];
                ph[0] = p01[2 * ks];
                ph[1] = p23[2 * ks];
                ph[2] = p01[2 * ks + 1];
                ph[3] = p23[2 * ks + 1];
                #pragma unroll
                for (int np = 0; np < 4; np++) {
                    uint32_t vh[4], vl[4];
                    uint32_t voff = (uint32_t)((ks * 16 + ((lane >> 3) & 1) * 8 + (lane & 7)) * AT_PITCHB
                                               + np * 32 + (lane >> 4) * 16);
                    ldm_x4t(vh, st + 2 * AT_KARR + voff);
                    ldm_x4t(vl, st + 3 * AT_KARR + voff);
                    mma_f16(o[2 * np],     ph, &vh[0]);
                    mma_f16(o[2 * np],     ph, &vl[0]);
                    mma_f16(o[2 * np + 1], ph, &vh[2]);
                    mma_f16(o[2 * np + 1], ph, &vl[2]);
                }
                mma_f16(ol, ph, vone);
            }
        }
    }

    // ---- finalize: divide by l, store single fp16 ----
    const float inv0 = 1.0f / ol[0];
    const float inv1 = 1.0f / ol[2];
    const int r0 = qrow0 + wm + (lane >> 2);
    const int qc = (lane & 3) * 2;
    #pragma unroll
    for (int n = 0; n < 8; n++) {
        int col = colh + n * 8 + qc;
        *(uint32_t*)&OF[(size_t)r0 * DMODEL + col] =
            cvt_f16x2(o[n][0] * inv0, o[n][1] * inv0);
        *(uint32_t*)&OF[(size_t)(r0 + 8) * DMODEL + col] =
            cvt_f16x2(o[n][2] * inv1, o[n][3] * inv1);
    }
}

// ---------------------------------------------------------------------------
extern "C" void kernel_launch(void* const* d_in, const int* in_sizes, int n_in,
                              void* d_out, int out_size)
{
    const float* x  = (const float*)d_in[0];
    const float* Wq = (const float*)d_in[1];
    const float* bq = (const float*)d_in[2];
    const float* Wk = (const float*)d_in[3];
    const float* bk = (const float*)d_in[4];
    const float* Wv = (const float*)d_in[5];
    const float* bv = (const float*)d_in[6];
    const float* Wo = (const float*)d_in[7];
    const float* bo = (const float*)d_in[8];
    float* out = (float*)d_out;

    __half *a16, *wthi, *wtlo, *q16, *khi, *klo, *vhi, *vlo;
    cudaGetSymbolAddress((void**)&a16, g_a16);
    cudaGetSymbolAddress((void**)&wthi, g_wthi);
    cudaGetSymbolAddress((void**)&wtlo, g_wtlo);
    cudaGetSymbolAddress((void**)&q16, g_q16);
    cudaGetSymbolAddress((void**)&khi, g_khi);
    cudaGetSymbolAddress((void**)&klo, g_klo);
    cudaGetSymbolAddress((void**)&vhi, g_vhi);
    cudaGetSymbolAddress((void**)&vlo, g_vlo);

    cudaFuncSetAttribute(gemm_f16, cudaFuncAttributeMaxDynamicSharedMemorySize, GS_TOTAL);
    cudaFuncSetAttribute(attn_mma, cudaFuncAttributeMaxDynamicSharedMemorySize, AT_SMEM);

    const int WSZ = DMODEL * DMODEL;

    // 1) one launch: x -> fp16 (z=4) + transpose/split 4 weights (z=0..3)
    conv_all<<<dim3(32, 32, 5), 256>>>(x, Wq, Wk, Wv, Wo, a16, wthi, wtlo);

    // 2) fused QKV projection: Q single (scaled), K/V split fp16
    gemm_f16<<<dim3(24, 32), 256, GS_TOTAL>>>(
        a16, wthi, wtlo, bq, bk, bv,
        nullptr, q16, khi, klo, vhi, vlo, 1);

    // 3) fp16 attention -> single fp16 output into a16
    attn_mma<<<dim3(S_LEN / 128, NHEAD, BATCH), 256, AT_SMEM>>>(
        q16, khi, klo, vhi, vlo, a16);

    // 4) output projection -> fp32 final
    gemm_f16<<<dim3(8, 32), 256, GS_TOTAL>>>(
        a16, wthi + 3 * WSZ, wtlo + 3 * WSZ, bo, bo, bo,
        out, nullptr, nullptr, nullptr, nullptr, nullptr, 0);
}

// round 16
// speedup vs baseline: 1.0586x; 1.0200x over previous
#include <cuda_runtime.h>
#include <cuda_bf16.h>
#include <cuda_fp16.h>
#include <cstdint>

#define S_LEN  2048
#define BATCH  2
#define DMODEL 1024
#define NHEAD  16
#define DHEAD  64
#define MROWS  (BATCH * S_LEN)   // 4096

// Scratch (allocation-free rule: device globals). All fp16.
__device__ __half g_a16 [MROWS * DMODEL];        // activations single fp16 (x, then attn out)
__device__ __half g_wthi[4 * DMODEL * DMODEL];   // W^T hi: Wq,Wk,Wv,Wo
__device__ __half g_wtlo[4 * DMODEL * DMODEL];   // W^T lo
__device__ __half g_q16 [MROWS * DMODEL];        // Q single fp16, scaled 0.125*log2e
__device__ __half g_khi [MROWS * DMODEL];        // K 2-term split
__device__ __half g_klo [MROWS * DMODEL];
__device__ __half g_vhi [MROWS * DMODEL];        // V 2-term split
__device__ __half g_vlo [MROWS * DMODEL];

// ============================ helpers ======================================
__device__ __forceinline__ uint32_t smem_u32(const void* p) {
    uint32_t a;
    asm("{ .reg .u64 t; cvta.to.shared.u64 t, %1; cvt.u32.u64 %0, t; }" : "=r"(a) : "l"(p));
    return a;
}
__device__ __forceinline__ void ldm_x4(uint32_t* r, uint32_t addr) {
    asm volatile("ldmatrix.sync.aligned.m8n8.x4.shared.b16 {%0,%1,%2,%3}, [%4];"
                 : "=r"(r[0]), "=r"(r[1]), "=r"(r[2]), "=r"(r[3]) : "r"(addr));
}
__device__ __forceinline__ void ldm_x4t(uint32_t* r, uint32_t addr) {
    asm volatile("ldmatrix.sync.aligned.m8n8.x4.trans.shared.b16 {%0,%1,%2,%3}, [%4];"
                 : "=r"(r[0]), "=r"(r[1]), "=r"(r[2]), "=r"(r[3]) : "r"(addr));
}
__device__ __forceinline__ void mma_f16(float* c, const uint32_t* a, const uint32_t* b) {
    asm volatile("mma.sync.aligned.m16n8k16.row.col.f32.f16.f16.f32 "
                 "{%0,%1,%2,%3}, {%4,%5,%6,%7}, {%8,%9}, {%0,%1,%2,%3};"
                 : "+f"(c[0]), "+f"(c[1]), "+f"(c[2]), "+f"(c[3])
                 : "r"(a[0]), "r"(a[1]), "r"(a[2]), "r"(a[3]), "r"(b[0]), "r"(b[1]));
}
__device__ __forceinline__ float ex2(float x) {
    float y;
    asm("ex2.approx.f32 %0, %1;" : "=f"(y) : "f"(x));
    return y;
}
__device__ __forceinline__ uint32_t h2ex2(uint32_t x) {
    uint32_t y;
    asm("ex2.approx.f16x2 %0, %1;" : "=r"(y) : "r"(x));
    return y;
}
__device__ __forceinline__ void split_pack2_f16(float v0, float v1, uint32_t& hp, uint32_t& lp) {
    __half h0 = __float2half_rn(v0);
    __half h1 = __float2half_rn(v1);
    __half l0 = __float2half_rn(v0 - __half2float(h0));
    __half l1 = __float2half_rn(v1 - __half2float(h1));
    hp = (uint32_t)__half_as_ushort(h0) | ((uint32_t)__half_as_ushort(h1) << 16);
    lp = (uint32_t)__half_as_ushort(l0) | ((uint32_t)__half_as_ushort(l1) << 16);
}
__device__ __forceinline__ uint32_t cvt_f16x2(float v0, float v1) {
    uint32_t r;
    asm("cvt.rn.f16x2.f32 %0, %1, %2;" : "=r"(r) : "f"(v1), "f"(v0));
    return r;
}
__device__ __forceinline__ void cp_async16(uint32_t dst, const void* src) {
    asm volatile("cp.async.cg.shared.global [%0], [%1], 16;" :: "r"(dst), "l"(src));
}
#define CP_COMMIT() asm volatile("cp.async.commit_group;" ::: "memory")
#define CP_WAIT(N)  asm volatile("cp.async.wait_group %0;" :: "n"(N) : "memory")

#define LOG2E 1.4426950408889634f

// ===========================================================================
// Merged pre-convert: blockIdx.z < 4 -> transpose+split weight z;
//                     blockIdx.z == 4 -> x -> single fp16 (grid-stride).
// ===========================================================================
__global__ __launch_bounds__(256) void conv_all(
    const float* __restrict__ X,
    const float* __restrict__ W0, const float* __restrict__ W1,
    const float* __restrict__ W2, const float* __restrict__ W3,
    __half* __restrict__ a16,
    __half* __restrict__ hiB, __half* __restrict__ loB)
{
    const int z = blockIdx.z;
    if (z == 4) {
        const int n4 = MROWS * DMODEL / 4;
        int base = (blockIdx.y * gridDim.x + blockIdx.x) * 256 + threadIdx.x;
        const int stride = gridDim.x * gridDim.y * 256;
        for (int i = base; i < n4; i += stride) {
            float4 v = ((const float4*)X)[i];
            uint2 o;
            o.x = cvt_f16x2(v.x, v.y);
            o.y = cvt_f16x2(v.z, v.w);
            ((uint2*)a16)[i] = o;
        }
        return;
    }

    __shared__ float t[32][33];
    const float* W = (z == 0) ? W0 : (z == 1) ? W1 : (z == 2) ? W2 : W3;
    __half* hi = hiB + (size_t)z * DMODEL * DMODEL;
    __half* lo = loB + (size_t)z * DMODEL * DMODEL;
    const int bk = blockIdx.x * 32;
    const int bn = blockIdx.y * 32;
    const int tx = threadIdx.x & 31;
    const int ty = threadIdx.x >> 5;   // 0..7
    #pragma unroll
    for (int j = 0; j < 4; j++)
        t[ty + 8 * j][tx] = W[(size_t)(bk + ty + 8 * j) * DMODEL + bn + tx];
    __syncthreads();
    #pragma unroll
    for (int j = 0; j < 4; j++) {
        float v = t[tx][ty + 8 * j];
        __half h = __float2half_rn(v);
        __half l = __float2half_rn(v - __half2float(h));
        size_t o = (size_t)(bn + ty + 8 * j) * DMODEL + bk + tx;
        hi[o] = h;
        lo[o] = l;
    }
}

// ===========================================================================
// Persistent cp.async 3-stage fp16 HMMA GEMM (single x split 2-term).
// Each CTA processes tiles_per_cta tiles (t = bx + i*gridDim.x) with a
// CONTINUOUS stage ring across tile boundaries (global chunk counter g,
// stage g%3) -> zero inter-tile pipeline drain, one balanced wave.
// Tile map: sel = t>>8, n0 = (t&7)*128, m0 = ((t>>3)&31)*128.
// Tiles t, t+256, t+512 share the same A-tile -> L1/L2 reuse.
// ===========================================================================
#define GS_ARR   10240
#define GS_STAGE 30720
#define GS_TOTAL 92160            // 3 stages

__global__ __launch_bounds__(256, 2) void gemm_f16(
    const __half* __restrict__ A,
    const __half* __restrict__ BhiB, const __half* __restrict__ BloB,
    const float* __restrict__ bv0, const float* __restrict__ bv1, const float* __restrict__ bv2,
    float* __restrict__ C,
    __half* __restrict__ Q,
    __half* __restrict__ KH, __half* __restrict__ KL,
    __half* __restrict__ VH, __half* __restrict__ VL,
    int mode, int tpc)
{
    extern __shared__ __align__(16) __half smb[];

    const int tid  = threadIdx.x;
    const int wid  = tid >> 5;
    const int lane = tid & 31;
    const int wm = (wid >> 2) * 64;
    const int wn = (wid & 3) * 32;
    const uint32_t sb = smem_u32(smb);
    const int NP = gridDim.x;

    float acc[4][4][4] = {};

    // load chunk (global counter g) into stage s
    auto load_g = [&](int s, int g) {
        const int ti = g >> 5, ch = g & 31;
        const int t  = blockIdx.x + ti * NP;
        const int sel = t >> 8;
        const int n0  = (t & 7) * 128;
        const int m0  = ((t >> 3) & 31) * 128;
        const __half* Bh = BhiB + ((size_t)sel << 20);
        const __half* Bl = BloB + ((size_t)sel << 20);
        const int kb = ch * 32;
        #pragma unroll
        for (int u = 0; u < 6; u++) {
            const int arr = u >> 1;                // 0=A, 1=Bhi, 2=Blo
            const int rem = tid + (u & 1) * 256;   // 0..511
            const int r = rem >> 2, c = rem & 3;
            uint32_t dst = sb + (uint32_t)(s * GS_STAGE + arr * GS_ARR + r * 80 + c * 16);
            const __half* gp;
            if      (arr == 0) gp = A  + (size_t)(m0 + r) * DMODEL + kb + c * 8;
            else if (arr == 1) gp = Bh + (size_t)(n0 + r) * DMODEL + kb + c * 8;
            else               gp = Bl + (size_t)(n0 + r) * DMODEL + kb + c * 8;
            cp_async16(dst, gp);
        }
    };

    auto compute = [&](int s) {
        const uint32_t base = sb + s * GS_STAGE;
        #pragma unroll
        for (int ks = 0; ks < 2; ks++) {
            uint32_t bh[2][4], bl[2][4];
            #pragma unroll
            for (int np = 0; np < 2; np++) {
                uint32_t off = (uint32_t)((wn + np * 16 + (lane >> 4) * 8 + (lane & 7)) * 80
                                          + ((lane >> 3) & 1) * 16 + ks * 32);
                ldm_x4(bh[np], base + 1 * GS_ARR + off);
                ldm_x4(bl[np], base + 2 * GS_ARR + off);
            }
            #pragma unroll
            for (int mi = 0; mi < 4; mi++) {
                uint32_t a[4];
                uint32_t off = (uint32_t)((wm + mi * 16 + (lane & 15)) * 80
                                          + (ks * 16 + ((lane >> 4) & 1) * 8) * 2);
                ldm_x4(a, base + off);
                #pragma unroll
                for (int np = 0; np < 2; np++) {
                    mma_f16(acc[mi][2 * np],     a, &bh[np][0]);
                    mma_f16(acc[mi][2 * np],     a, &bl[np][0]);
                    mma_f16(acc[mi][2 * np + 1], a, &bh[np][2]);
                    mma_f16(acc[mi][2 * np + 1], a, &bl[np][2]);
                }
            }
        }
    };

    const int qrow = lane >> 2;
    const int qcol = (lane & 3) * 2;

    auto epilogue = [&](int t) {
        const int sel = t >> 8;
        const int n0  = (t & 7) * 128;
        const int m0  = ((t >> 3) & 31) * 128;
        const float* bias = (sel == 0) ? bv0 : (sel == 1) ? bv1 : bv2;
        if (mode == 0) {
            #pragma unroll
            for (int mi = 0; mi < 4; mi++) {
                #pragma unroll
                for (int ni = 0; ni < 4; ni++) {
                    int col = n0 + wn + ni * 8 + qcol;
                    float2 bb = *(const float2*)&bias[col];
                    int r0 = m0 + wm + mi * 16 + qrow;
                    *(float2*)&C[(size_t)r0 * DMODEL + col] =
                        make_float2(acc[mi][ni][0] + bb.x, acc[mi][ni][1] + bb.y);
                    *(float2*)&C[(size_t)(r0 + 8) * DMODEL + col] =
                        make_float2(acc[mi][ni][2] + bb.x, acc[mi][ni][3] + bb.y);
                }
            }
        } else if (sel == 0) {
            const float scl = 0.125f * LOG2E;
            #pragma unroll
            for (int mi = 0; mi < 4; mi++) {
                #pragma unroll
                for (int ni = 0; ni < 4; ni++) {
                    int col = n0 + wn + ni * 8 + qcol;
                    float2 bb = *(const float2*)&bias[col];
                    int r0 = m0 + wm + mi * 16 + qrow;
                    *(uint32_t*)&Q[(size_t)r0 * DMODEL + col] =
                        cvt_f16x2((acc[mi][ni][0] + bb.x) * scl, (acc[mi][ni][1] + bb.y) * scl);
                    *(uint32_t*)&Q[(size_t)(r0 + 8) * DMODEL + col] =
                        cvt_f16x2((acc[mi][ni][2] + bb.x) * scl, (acc[mi][ni][3] + bb.y) * scl);
                }
            }
        } else {
            __half* H = (sel == 1) ? KH : VH;
            __half* L = (sel == 1) ? KL : VL;
            #pragma unroll
            for (int mi = 0; mi < 4; mi++) {
                #pragma unroll
                for (int ni = 0; ni < 4; ni++) {
                    int col = n0 + wn + ni * 8 + qcol;
                    float2 bb = *(const float2*)&bias[col];
                    int r0 = m0 + wm + mi * 16 + qrow;
                    uint32_t hp, lp;
                    split_pack2_f16(acc[mi][ni][0] + bb.x, acc[mi][ni][1] + bb.y, hp, lp);
                    *(uint32_t*)&H[(size_t)r0 * DMODEL + col] = hp;
                    *(uint32_t*)&L[(size_t)r0 * DMODEL + col] = lp;
                    split_pack2_f16(acc[mi][ni][2] + bb.x, acc[mi][ni][3] + bb.y, hp, lp);
                    *(uint32_t*)&H[(size_t)(r0 + 8) * DMODEL + col] = hp;
                    *(uint32_t*)&L[(size_t)(r0 + 8) * DMODEL + col] = lp;
                }
            }
        }
    };

    const int G = tpc * 32;   // total chunks across all this CTA's tiles
    load_g(0, 0);
    CP_COMMIT();
    for (int g = 0; g < G; g++) {
        if (g + 1 < G) load_g((g + 1) % 3, g + 1);
        CP_COMMIT();
        CP_WAIT(1);
        __syncthreads();
        compute(g % 3);
        if ((g & 31) == 31) {
            epilogue(blockIdx.x + (g >> 5) * NP);
            #pragma unroll
            for (int mi = 0; mi < 4; mi++)
                #pragma unroll
                for (int ni = 0; ni < 4; ni++)
                    #pragma unroll
                    for (int q = 0; q < 4; q++) acc[mi][ni][q] = 0.0f;
        }
    }
}

// ===========================================================================
// fp16 HMMA flash attention (causal), exp2 softmax with ex2.approx.f16x2 —
// exact R13/R15 structure (proven 132us / rel_err 5.1e-4).
// ===========================================================================
#define AT_PITCHB 144            // 72 halfs * 2B per row (64 data + 8 pad)
#define AT_KARR   9216           // 64*144
#define AT_STAGE  36864          // Khi|Klo|Vhi|Vlo
#define AT_SMEM   (3*AT_STAGE)   // 110592

__global__ __launch_bounds__(256, 2) void attn_mma(
    const __half* __restrict__ Q16,
    const __half* __restrict__ Khi, const __half* __restrict__ Klo,
    const __half* __restrict__ Vhi, const __half* __restrict__ Vlo,
    __half* __restrict__ OF)
{
    extern __shared__ __align__(16) char sma[];
    const uint32_t sb = smem_u32(sma);

    const int qq = (int)(gridDim.x - 1) - (int)blockIdx.x;  // longest first
    const int h  = blockIdx.y;
    const int b  = blockIdx.z;
    const int tid  = threadIdx.x;
    const int wid  = tid >> 5;
    const int lane = tid & 31;
    const int wm = wid * 16;
    const int colh = h * DHEAD;
    const int qrow0 = b * S_LEN + qq * 128;

    // ---- prologue A: stream Q (single) into stage-0 region via cp.async ----
    #pragma unroll
    for (int t = 0; t < 4; t++) {
        const int rem = tid + t * 256;
        const int r = rem >> 3, c = rem & 7;
        uint32_t dst = sb + (uint32_t)(r * AT_PITCHB + c * 16);
        cp_async16(dst, Q16 + (size_t)(qrow0 + r) * DMODEL + colh + c * 8);
    }
    CP_COMMIT();
    CP_WAIT(0);
    __syncthreads();

    // ---- prologue B: Q fragments -> registers ----
    uint32_t qr[4][4];
    #pragma unroll
    for (int ks = 0; ks < 4; ks++) {
        uint32_t qoff = (uint32_t)((wm + (lane & 15)) * AT_PITCHB
                                   + ((lane >> 4) & 1) * 16 + ks * 32);
        ldm_x4(qr[ks], sb + qoff);
    }
    __syncthreads();   // Q reads complete before stage-0 K/V overwrite

    const uint32_t vone[2] = { 0x3C003C00u, 0x3C003C00u };

    auto load_stage = [&](int s, int kt) {
        const int key0 = kt * 64;
        #pragma unroll
        for (int t = 0; t < 8; t++) {
            const int arr = t >> 1;
            const int rem = tid + (t & 1) * 256;
            const int r = rem >> 3, c = rem & 7;
            uint32_t dst = sb + s * AT_STAGE + arr * AT_KARR
                         + (uint32_t)(r * AT_PITCHB + c * 16);
            const __half* g;
            if      (arr == 0) g = Khi + (size_t)(b * S_LEN + key0 + r) * DMODEL + colh + c * 8;
            else if (arr == 1) g = Klo + (size_t)(b * S_LEN + key0 + r) * DMODEL + colh + c * 8;
            else if (arr == 2) g = Vhi + (size_t)(b * S_LEN + key0 + r) * DMODEL + colh + c * 8;
            else               g = Vlo + (size_t)(b * S_LEN + key0 + r) * DMODEL + colh + c * 8;
            cp_async16(dst, g);
        }
    };

    const int nkt = 2 * qq + 2;
    load_stage(0, 0);
    CP_COMMIT();

    float o[8][4] = {};
    float ol[4] = {};                 // ones-fragment accumulator (l carrier)
    float m0 = -1e30f, m1 = -1e30f;

    for (int kt = 0; kt < nkt; kt++) {
        if (kt + 1 < nkt) load_stage((kt + 1) % 3, kt + 1);
        CP_COMMIT();
        CP_WAIT(1);
        __syncthreads();              // ONE barrier per key tile

        if (kt * 64 <= qq * 128 + wm + 15) {
            const uint32_t st = sb + (kt % 3) * AT_STAGE;

            // ---- S = Q K^T (2-term: q*kh + q*kl; Q from registers) ----
            float sv[8][4] = {};
            #pragma unroll
            for (int ks = 0; ks < 4; ks++) {
                #pragma unroll
                for (int np = 0; np < 4; np++) {
                    uint32_t kh[4], kl[4];
                    uint32_t koff = (uint32_t)((np * 16 + (lane >> 4) * 8 + (lane & 7)) * AT_PITCHB
                                               + ((lane >> 3) & 1) * 16 + ks * 32);
                    ldm_x4(kh, st + koff);
                    ldm_x4(kl, st + AT_KARR + koff);
                    mma_f16(sv[2 * np],     qr[ks], &kh[0]);
                    mma_f16(sv[2 * np],     qr[ks], &kl[0]);
                    mma_f16(sv[2 * np + 1], qr[ks], &kh[2]);
                    mma_f16(sv[2 * np + 1], qr[ks], &kl[2]);
                }
            }

            // ---- causal mask ----
            if (kt * 64 + 63 > qq * 128) {
                const int rg0 = qq * 128 + wm + (lane >> 2);
                const int cg  = kt * 64 + (lane & 3) * 2;
                #pragma unroll
                for (int n = 0; n < 8; n++) {
                    int c0 = cg + n * 8, c1 = c0 + 1;
                    if (c0 > rg0)     sv[n][0] = -1e10f;
                    if (c1 > rg0)     sv[n][1] = -1e10f;
                    if (c0 > rg0 + 8) sv[n][2] = -1e10f;
                    if (c1 > rg0 + 8) sv[n][3] = -1e10f;
                }
            }

            // ---- online max update (quad shuffles) ----
            float rm0 = -1e30f, rm1 = -1e30f;
            #pragma unroll
            for (int n = 0; n < 8; n++) {
                rm0 = fmaxf(rm0, fmaxf(sv[n][0], sv[n][1]));
                rm1 = fmaxf(rm1, fmaxf(sv[n][2], sv[n][3]));
            }
            rm0 = fmaxf(rm0, __shfl_xor_sync(0xffffffffu, rm0, 1));
            rm0 = fmaxf(rm0, __shfl_xor_sync(0xffffffffu, rm0, 2));
            rm1 = fmaxf(rm1, __shfl_xor_sync(0xffffffffu, rm1, 1));
            rm1 = fmaxf(rm1, __shfl_xor_sync(0xffffffffu, rm1, 2));
            float mn0 = fmaxf(m0, rm0), mn1 = fmaxf(m1, rm1);
            float a0 = ex2(m0 - mn0), a1 = ex2(m1 - mn1);
            m0 = mn0; m1 = mn1;

            // ---- P = exp2(S - m): fp32 diff -> f16x2 pack -> ex2.f16x2 ----
            uint32_t p01[8], p23[8];
            #pragma unroll
            for (int n = 0; n < 8; n++) {
                p01[n] = h2ex2(cvt_f16x2(sv[n][0] - mn0, sv[n][1] - mn0));
                p23[n] = h2ex2(cvt_f16x2(sv[n][2] - mn1, sv[n][3] - mn1));
                o[n][0] *= a0; o[n][1] *= a0;
                o[n][2] *= a1; o[n][3] *= a1;
            }
            ol[0] *= a0; ol[1] *= a0; ol[2] *= a1; ol[3] *= a1;

            // ---- O += P V; l += P @ ones (constant fragment) ----
            #pragma unroll
            for (int ks = 0; ks < 4; ks++) {
                uint32_t ph[4];
                ph[0] = p01[2 * ks];
                ph[1] = p23[2 * ks];
                ph[2] = p01[2 * ks + 1];
                ph[3] = p23[2 * ks + 1];
                #pragma unroll
                for (int np = 0; np < 4; np++) {
                    uint32_t vh[4], vl[4];
                    uint32_t voff = (uint32_t)((ks * 16 + ((lane >> 3) & 1) * 8 + (lane & 7)) * AT_PITCHB
                                               + np * 32 + (lane >> 4) * 16);
                    ldm_x4t(vh, st + 2 * AT_KARR + voff);
                    ldm_x4t(vl, st + 3 * AT_KARR + voff);
                    mma_f16(o[2 * np],     ph, &vh[0]);
                    mma_f16(o[2 * np],     ph, &vl[0]);
                    mma_f16(o[2 * np + 1], ph, &vh[2]);
                    mma_f16(o[2 * np + 1], ph, &vl[2]);
                }
                mma_f16(ol, ph, vone);
            }
        }
    }

    // ---- finalize: divide by l, store single fp16 ----
    const float inv0 = 1.0f / ol[0];
    const float inv1 = 1.0f / ol[2];
    const int r0 = qrow0 + wm + (lane >> 2);
    const int qc = (lane & 3) * 2;
    #pragma unroll
    for (int n = 0; n < 8; n++) {
        int col = colh + n * 8 + qc;
        *(uint32_t*)&OF[(size_t)r0 * DMODEL + col] =
            cvt_f16x2(o[n][0] * inv0, o[n][1] * inv0);
        *(uint32_t*)&OF[(size_t)(r0 + 8) * DMODEL + col] =
            cvt_f16x2(o[n][2] * inv1, o[n][3] * inv1);
    }
}

// ---------------------------------------------------------------------------
extern "C" void kernel_launch(void* const* d_in, const int* in_sizes, int n_in,
                              void* d_out, int out_size)
{
    const float* x  = (const float*)d_in[0];
    const float* Wq = (const float*)d_in[1];
    const float* bq = (const float*)d_in[2];
    const float* Wk = (const float*)d_in[3];
    const float* bk = (const float*)d_in[4];
    const float* Wv = (const float*)d_in[5];
    const float* bv = (const float*)d_in[6];
    const float* Wo = (const float*)d_in[7];
    const float* bo = (const float*)d_in[8];
    float* out = (float*)d_out;

    __half *a16, *wthi, *wtlo, *q16, *khi, *klo, *vhi, *vlo;
    cudaGetSymbolAddress((void**)&a16, g_a16);
    cudaGetSymbolAddress((void**)&wthi, g_wthi);
    cudaGetSymbolAddress((void**)&wtlo, g_wtlo);
    cudaGetSymbolAddress((void**)&q16, g_q16);
    cudaGetSymbolAddress((void**)&khi, g_khi);
    cudaGetSymbolAddress((void**)&klo, g_klo);
    cudaGetSymbolAddress((void**)&vhi, g_vhi);
    cudaGetSymbolAddress((void**)&vlo, g_vlo);

    cudaFuncSetAttribute(gemm_f16, cudaFuncAttributeMaxDynamicSharedMemorySize, GS_TOTAL);
    cudaFuncSetAttribute(attn_mma, cudaFuncAttributeMaxDynamicSharedMemorySize, AT_SMEM);

    const int WSZ = DMODEL * DMODEL;

    // 1) one launch: x -> fp16 (z=4) + transpose/split 4 weights (z=0..3)
    conv_all<<<dim3(32, 32, 5), 256>>>(x, Wq, Wk, Wv, Wo, a16, wthi, wtlo);

    // 2) persistent fused QKV projection: 256 CTAs x 3 tiles (Q/K/V share A)
    gemm_f16<<<256, 256, GS_TOTAL>>>(
        a16, wthi, wtlo, bq, bk, bv,
        nullptr, q16, khi, klo, vhi, vlo, 1, 3);

    // 3) fp16 attention -> single fp16 output into a16
    attn_mma<<<dim3(S_LEN / 128, NHEAD, BATCH), 256, AT_SMEM>>>(
        q16, khi, klo, vhi, vlo, a16);

    // 4) output projection: 256 CTAs x 1 tile -> fp32 final
    gemm_f16<<<256, 256, GS_TOTAL>>>(
        a16, wthi + 3 * WSZ, wtlo + 3 * WSZ, bo, bo, bo,
        out, nullptr, nullptr, nullptr, nullptr, nullptr, 0, 1);
}

// round 17
// speedup vs baseline: 1.2983x; 1.2265x over previous
#include <cuda_runtime.h>
#include <cuda_bf16.h>
#include <cuda_fp16.h>
#include <cstdint>

#define S_LEN  2048
#define BATCH  2
#define DMODEL 1024
#define NHEAD  16
#define DHEAD  64
#define MROWS  (BATCH * S_LEN)   // 4096

// Scratch (allocation-free rule: device globals). All fp16.
__device__ __half g_a16 [MROWS * DMODEL];        // activations single fp16 (x, then attn out)
__device__ __half g_wthi[4 * DMODEL * DMODEL];   // W^T hi: Wq,Wk,Wv,Wo
__device__ __half g_wtlo[4 * DMODEL * DMODEL];   // W^T lo
__device__ __half g_q16 [MROWS * DMODEL];        // Q single fp16, scaled 0.125*log2e
__device__ __half g_k16 [MROWS * DMODEL];        // K single fp16
__device__ __half g_v16 [MROWS * DMODEL];        // V single fp16

// ============================ helpers ======================================
__device__ __forceinline__ uint32_t smem_u32(const void* p) {
    uint32_t a;
    asm("{ .reg .u64 t; cvta.to.shared.u64 t, %1; cvt.u32.u64 %0, t; }" : "=r"(a) : "l"(p));
    return a;
}
__device__ __forceinline__ void ldm_x4(uint32_t* r, uint32_t addr) {
    asm volatile("ldmatrix.sync.aligned.m8n8.x4.shared.b16 {%0,%1,%2,%3}, [%4];"
                 : "=r"(r[0]), "=r"(r[1]), "=r"(r[2]), "=r"(r[3]) : "r"(addr));
}
__device__ __forceinline__ void ldm_x4t(uint32_t* r, uint32_t addr) {
    asm volatile("ldmatrix.sync.aligned.m8n8.x4.trans.shared.b16 {%0,%1,%2,%3}, [%4];"
                 : "=r"(r[0]), "=r"(r[1]), "=r"(r[2]), "=r"(r[3]) : "r"(addr));
}
__device__ __forceinline__ void mma_f16(float* c, const uint32_t* a, const uint32_t* b) {
    asm volatile("mma.sync.aligned.m16n8k16.row.col.f32.f16.f16.f32 "
                 "{%0,%1,%2,%3}, {%4,%5,%6,%7}, {%8,%9}, {%0,%1,%2,%3};"
                 : "+f"(c[0]), "+f"(c[1]), "+f"(c[2]), "+f"(c[3])
                 : "r"(a[0]), "r"(a[1]), "r"(a[2]), "r"(a[3]), "r"(b[0]), "r"(b[1]));
}
__device__ __forceinline__ float ex2(float x) {
    float y;
    asm("ex2.approx.f32 %0, %1;" : "=f"(y) : "f"(x));
    return y;
}
__device__ __forceinline__ uint32_t h2ex2(uint32_t x) {
    uint32_t y;
    asm("ex2.approx.f16x2 %0, %1;" : "=r"(y) : "r"(x));
    return y;
}
__device__ __forceinline__ uint32_t cvt_f16x2(float v0, float v1) {
    uint32_t r;
    asm("cvt.rn.f16x2.f32 %0, %1, %2;" : "=r"(r) : "f"(v1), "f"(v0));
    return r;
}
__device__ __forceinline__ void cp_async16(uint32_t dst, const void* src) {
    asm volatile("cp.async.cg.shared.global [%0], [%1], 16;" :: "r"(dst), "l"(src));
}
#define CP_COMMIT() asm volatile("cp.async.commit_group;" ::: "memory")
#define CP_WAIT(N)  asm volatile("cp.async.wait_group %0;" :: "n"(N) : "memory")

#define LOG2E 1.4426950408889634f

// ===========================================================================
// Merged pre-convert: blockIdx.z < 4 -> transpose+split weight z;
//                     blockIdx.z == 4 -> x -> single fp16 (grid-stride).
// ===========================================================================
__global__ __launch_bounds__(256) void conv_all(
    const float* __restrict__ X,
    const float* __restrict__ W0, const float* __restrict__ W1,
    const float* __restrict__ W2, const float* __restrict__ W3,
    __half* __restrict__ a16,
    __half* __restrict__ hiB, __half* __restrict__ loB)
{
    const int z = blockIdx.z;
    if (z == 4) {
        const int n4 = MROWS * DMODEL / 4;
        int base = (blockIdx.y * gridDim.x + blockIdx.x) * 256 + threadIdx.x;
        const int stride = gridDim.x * gridDim.y * 256;
        for (int i = base; i < n4; i += stride) {
            float4 v = ((const float4*)X)[i];
            uint2 o;
            o.x = cvt_f16x2(v.x, v.y);
            o.y = cvt_f16x2(v.z, v.w);
            ((uint2*)a16)[i] = o;
        }
        return;
    }

    __shared__ float t[32][33];
    const float* W = (z == 0) ? W0 : (z == 1) ? W1 : (z == 2) ? W2 : W3;
    __half* hi = hiB + (size_t)z * DMODEL * DMODEL;
    __half* lo = loB + (size_t)z * DMODEL * DMODEL;
    const int bk = blockIdx.x * 32;
    const int bn = blockIdx.y * 32;
    const int tx = threadIdx.x & 31;
    const int ty = threadIdx.x >> 5;   // 0..7
    #pragma unroll
    for (int j = 0; j < 4; j++)
        t[ty + 8 * j][tx] = W[(size_t)(bk + ty + 8 * j) * DMODEL + bn + tx];
    __syncthreads();
    #pragma unroll
    for (int j = 0; j < 4; j++) {
        float v = t[tx][ty + 8 * j];
        __half h = __float2half_rn(v);
        __half l = __float2half_rn(v - __half2float(h));
        size_t o = (size_t)(bn + ty + 8 * j) * DMODEL + bk + tx;
        hi[o] = h;
        lo[o] = l;
    }
}

// ===========================================================================
// Persistent cp.async 3-stage fp16 HMMA GEMM (single x split 2-term).
// Tile map: sel = t>>8, n0 = (t&7)*128, m0 = ((t>>3)&31)*128.
// mode 0: fp32 out. mode 1: all outputs single fp16 (Q scaled 0.125*log2e).
// ===========================================================================
#define GS_ARR   10240
#define GS_STAGE 30720
#define GS_TOTAL 92160            // 3 stages

__global__ __launch_bounds__(256, 2) void gemm_f16(
    const __half* __restrict__ A,
    const __half* __restrict__ BhiB, const __half* __restrict__ BloB,
    const float* __restrict__ bv0, const float* __restrict__ bv1, const float* __restrict__ bv2,
    float* __restrict__ C,
    __half* __restrict__ Qo, __half* __restrict__ Ko, __half* __restrict__ Vo,
    int mode, int tpc)
{
    extern __shared__ __align__(16) __half smb[];

    const int tid  = threadIdx.x;
    const int wid  = tid >> 5;
    const int lane = tid & 31;
    const int wm = (wid >> 2) * 64;
    const int wn = (wid & 3) * 32;
    const uint32_t sb = smem_u32(smb);
    const int NP = gridDim.x;

    float acc[4][4][4] = {};

    auto load_g = [&](int s, int g) {
        const int ti = g >> 5, ch = g & 31;
        const int t  = blockIdx.x + ti * NP;
        const int sel = t >> 8;
        const int n0  = (t & 7) * 128;
        const int m0  = ((t >> 3) & 31) * 128;
        const __half* Bh = BhiB + ((size_t)sel << 20);
        const __half* Bl = BloB + ((size_t)sel << 20);
        const int kb = ch * 32;
        #pragma unroll
        for (int u = 0; u < 6; u++) {
            const int arr = u >> 1;
            const int rem = tid + (u & 1) * 256;
            const int r = rem >> 2, c = rem & 3;
            uint32_t dst = sb + (uint32_t)(s * GS_STAGE + arr * GS_ARR + r * 80 + c * 16);
            const __half* gp;
            if      (arr == 0) gp = A  + (size_t)(m0 + r) * DMODEL + kb + c * 8;
            else if (arr == 1) gp = Bh + (size_t)(n0 + r) * DMODEL + kb + c * 8;
            else               gp = Bl + (size_t)(n0 + r) * DMODEL + kb + c * 8;
            cp_async16(dst, gp);
        }
    };

    auto compute = [&](int s) {
        const uint32_t base = sb + s * GS_STAGE;
        #pragma unroll
        for (int ks = 0; ks < 2; ks++) {
            uint32_t bh[2][4], bl[2][4];
            #pragma unroll
            for (int np = 0; np < 2; np++) {
                uint32_t off = (uint32_t)((wn + np * 16 + (lane >> 4) * 8 + (lane & 7)) * 80
                                          + ((lane >> 3) & 1) * 16 + ks * 32);
                ldm_x4(bh[np], base + 1 * GS_ARR + off);
                ldm_x4(bl[np], base + 2 * GS_ARR + off);
            }
            #pragma unroll
            for (int mi = 0; mi < 4; mi++) {
                uint32_t a[4];
                uint32_t off = (uint32_t)((wm + mi * 16 + (lane & 15)) * 80
                                          + (ks * 16 + ((lane >> 4) & 1) * 8) * 2);
                ldm_x4(a, base + off);
                #pragma unroll
                for (int np = 0; np < 2; np++) {
                    mma_f16(acc[mi][2 * np],     a, &bh[np][0]);
                    mma_f16(acc[mi][2 * np],     a, &bl[np][0]);
                    mma_f16(acc[mi][2 * np + 1], a, &bh[np][2]);
                    mma_f16(acc[mi][2 * np + 1], a, &bl[np][2]);
                }
            }
        }
    };

    const int qrow = lane >> 2;
    const int qcol = (lane & 3) * 2;

    auto epilogue = [&](int t) {
        const int sel = t >> 8;
        const int n0  = (t & 7) * 128;
        const int m0  = ((t >> 3) & 31) * 128;
        const float* bias = (sel == 0) ? bv0 : (sel == 1) ? bv1 : bv2;
        if (mode == 0) {
            #pragma unroll
            for (int mi = 0; mi < 4; mi++) {
                #pragma unroll
                for (int ni = 0; ni < 4; ni++) {
                    int col = n0 + wn + ni * 8 + qcol;
                    float2 bb = *(const float2*)&bias[col];
                    int r0 = m0 + wm + mi * 16 + qrow;
                    *(float2*)&C[(size_t)r0 * DMODEL + col] =
                        make_float2(acc[mi][ni][0] + bb.x, acc[mi][ni][1] + bb.y);
                    *(float2*)&C[(size_t)(r0 + 8) * DMODEL + col] =
                        make_float2(acc[mi][ni][2] + bb.x, acc[mi][ni][3] + bb.y);
                }
            }
        } else {
            const float scl = (sel == 0) ? (0.125f * LOG2E) : 1.0f;
            __half* O = (sel == 0) ? Qo : (sel == 1) ? Ko : Vo;
            #pragma unroll
            for (int mi = 0; mi < 4; mi++) {
                #pragma unroll
                for (int ni = 0; ni < 4; ni++) {
                    int col = n0 + wn + ni * 8 + qcol;
                    float2 bb = *(const float2*)&bias[col];
                    int r0 = m0 + wm + mi * 16 + qrow;
                    *(uint32_t*)&O[(size_t)r0 * DMODEL + col] =
                        cvt_f16x2((acc[mi][ni][0] + bb.x) * scl, (acc[mi][ni][1] + bb.y) * scl);
                    *(uint32_t*)&O[(size_t)(r0 + 8) * DMODEL + col] =
                        cvt_f16x2((acc[mi][ni][2] + bb.x) * scl, (acc[mi][ni][3] + bb.y) * scl);
                }
            }
        }
    };

    const int G = tpc * 32;
    load_g(0, 0);
    CP_COMMIT();
    for (int g = 0; g < G; g++) {
        if (g + 1 < G) load_g((g + 1) % 3, g + 1);
        CP_COMMIT();
        CP_WAIT(1);
        __syncthreads();
        compute(g % 3);
        if ((g & 31) == 31) {
            epilogue(blockIdx.x + (g >> 5) * NP);
            #pragma unroll
            for (int mi = 0; mi < 4; mi++)
                #pragma unroll
                for (int ni = 0; ni < 4; ni++)
                    #pragma unroll
                    for (int q = 0; q < 4; q++) acc[mi][ni][q] = 0.0f;
        }
    }
}

// ===========================================================================
// fp16 HMMA flash attention (causal), exp2 softmax (ex2.f16x2), ALL operands
// single fp16: Q in regs, K single, P single, V single. 3-stage K/V
// pipeline (stage = K|V, 18KB), ONE syncthreads per key tile; l via
// constant all-ones b-fragment MMA.
// ===========================================================================
#define AT_PITCHB 144            // 72 halfs * 2B per row (64 data + 8 pad)
#define AT_KARR   9216           // 64*144
#define AT_STAGE  18432          // K | V
#define AT_SMEM   (3*AT_STAGE)   // 55296

__global__ __launch_bounds__(256, 2) void attn_mma(
    const __half* __restrict__ Q16,
    const __half* __restrict__ K16, const __half* __restrict__ V16,
    __half* __restrict__ OF)
{
    extern __shared__ __align__(16) char sma[];
    const uint32_t sb = smem_u32(sma);

    const int qq = (int)(gridDim.x - 1) - (int)blockIdx.x;  // longest first
    const int h  = blockIdx.y;
    const int b  = blockIdx.z;
    const int tid  = threadIdx.x;
    const int wid  = tid >> 5;
    const int lane = tid & 31;
    const int wm = wid * 16;
    const int colh = h * DHEAD;
    const int qrow0 = b * S_LEN + qq * 128;

    // ---- prologue A: stream Q (single, 128x144B = one stage) ----
    #pragma unroll
    for (int t = 0; t < 4; t++) {
        const int rem = tid + t * 256;
        const int r = rem >> 3, c = rem & 7;
        uint32_t dst = sb + (uint32_t)(r * AT_PITCHB + c * 16);
        cp_async16(dst, Q16 + (size_t)(qrow0 + r) * DMODEL + colh + c * 8);
    }
    CP_COMMIT();
    CP_WAIT(0);
    __syncthreads();

    // ---- prologue B: Q fragments -> registers ----
    uint32_t qr[4][4];
    #pragma unroll
    for (int ks = 0; ks < 4; ks++) {
        uint32_t qoff = (uint32_t)((wm + (lane & 15)) * AT_PITCHB
                                   + ((lane >> 4) & 1) * 16 + ks * 32);
        ldm_x4(qr[ks], sb + qoff);
    }
    __syncthreads();   // Q reads complete before stage-0 K/V overwrite

    const uint32_t vone[2] = { 0x3C003C00u, 0x3C003C00u };

    auto load_stage = [&](int s, int kt) {
        const int key0 = kt * 64;
        #pragma unroll
        for (int t = 0; t < 4; t++) {
            const int arr = t >> 1;                // 0=K, 1=V
            const int rem = tid + (t & 1) * 256;   // 0..511
            const int r = rem >> 3, c = rem & 7;
            uint32_t dst = sb + s * AT_STAGE + arr * AT_KARR
                         + (uint32_t)(r * AT_PITCHB + c * 16);
            const __half* g = (arr == 0 ? K16 : V16)
                + (size_t)(b * S_LEN + key0 + r) * DMODEL + colh + c * 8;
            cp_async16(dst, g);
        }
    };

    const int nkt = 2 * qq + 2;
    load_stage(0, 0);
    CP_COMMIT();

    float o[8][4] = {};
    float ol[4] = {};                 // ones-fragment accumulator (l carrier)
    float m0 = -1e30f, m1 = -1e30f;

    for (int kt = 0; kt < nkt; kt++) {
        if (kt + 1 < nkt) load_stage((kt + 1) % 3, kt + 1);
        CP_COMMIT();
        CP_WAIT(1);
        __syncthreads();              // ONE barrier per key tile

        if (kt * 64 <= qq * 128 + wm + 15) {
            const uint32_t st = sb + (kt % 3) * AT_STAGE;

            // ---- S = Q K^T (single x single) ----
            float sv[8][4] = {};
            #pragma unroll
            for (int ks = 0; ks < 4; ks++) {
                #pragma unroll
                for (int np = 0; np < 4; np++) {
                    uint32_t kh[4];
                    uint32_t koff = (uint32_t)((np * 16 + (lane >> 4) * 8 + (lane & 7)) * AT_PITCHB
                                               + ((lane >> 3) & 1) * 16 + ks * 32);
                    ldm_x4(kh, st + koff);
                    mma_f16(sv[2 * np],     qr[ks], &kh[0]);
                    mma_f16(sv[2 * np + 1], qr[ks], &kh[2]);
                }
            }

            // ---- causal mask ----
            if (kt * 64 + 63 > qq * 128) {
                const int rg0 = qq * 128 + wm + (lane >> 2);
                const int cg  = kt * 64 + (lane & 3) * 2;
                #pragma unroll
                for (int n = 0; n < 8; n++) {
                    int c0 = cg + n * 8, c1 = c0 + 1;
                    if (c0 > rg0)     sv[n][0] = -1e10f;
                    if (c1 > rg0)     sv[n][1] = -1e10f;
                    if (c0 > rg0 + 8) sv[n][2] = -1e10f;
                    if (c1 > rg0 + 8) sv[n][3] = -1e10f;
                }
            }

            // ---- online max update (quad shuffles) ----
            float rm0 = -1e30f, rm1 = -1e30f;
            #pragma unroll
            for (int n = 0; n < 8; n++) {
                rm0 = fmaxf(rm0, fmaxf(sv[n][0], sv[n][1]));
                rm1 = fmaxf(rm1, fmaxf(sv[n][2], sv[n][3]));
            }
            rm0 = fmaxf(rm0, __shfl_xor_sync(0xffffffffu, rm0, 1));
            rm0 = fmaxf(rm0, __shfl_xor_sync(0xffffffffu, rm0, 2));
            rm1 = fmaxf(rm1, __shfl_xor_sync(0xffffffffu, rm1, 1));
            rm1 = fmaxf(rm1, __shfl_xor_sync(0xffffffffu, rm1, 2));
            float mn0 = fmaxf(m0, rm0), mn1 = fmaxf(m1, rm1);
            float a0 = ex2(m0 - mn0), a1 = ex2(m1 - mn1);
            m0 = mn0; m1 = mn1;

            // ---- P = exp2(S - m): fp32 diff -> f16x2 pack -> ex2.f16x2 ----
            uint32_t p01[8], p23[8];
            #pragma unroll
            for (int n = 0; n < 8; n++) {
                p01[n] = h2ex2(cvt_f16x2(sv[n][0] - mn0, sv[n][1] - mn0));
                p23[n] = h2ex2(cvt_f16x2(sv[n][2] - mn1, sv[n][3] - mn1));
                o[n][0] *= a0; o[n][1] *= a0;
                o[n][2] *= a1; o[n][3] *= a1;
            }
            ol[0] *= a0; ol[1] *= a0; ol[2] *= a1; ol[3] *= a1;

            // ---- O += P V (single V); l += P @ ones ----
            #pragma unroll
            for (int ks = 0; ks < 4; ks++) {
                uint32_t ph[4];
                ph[0] = p01[2 * ks];
                ph[1] = p23[2 * ks];
                ph[2] = p01[2 * ks + 1];
                ph[3] = p23[2 * ks + 1];
                #pragma unroll
                for (int np = 0; np < 4; np++) {
                    uint32_t vh[4];
                    uint32_t voff = (uint32_t)((ks * 16 + ((lane >> 3) & 1) * 8 + (lane & 7)) * AT_PITCHB
                                               + np * 32 + (lane >> 4) * 16);
                    ldm_x4t(vh, st + AT_KARR + voff);
                    mma_f16(o[2 * np],     ph, &vh[0]);
                    mma_f16(o[2 * np + 1], ph, &vh[2]);
                }
                mma_f16(ol, ph, vone);
            }
        }
    }

    // ---- finalize: divide by l, store single fp16 ----
    const float inv0 = 1.0f / ol[0];
    const float inv1 = 1.0f / ol[2];
    const int r0 = qrow0 + wm + (lane >> 2);
    const int qc = (lane & 3) * 2;
    #pragma unroll
    for (int n = 0; n < 8; n++) {
        int col = colh + n * 8 + qc;
        *(uint32_t*)&OF[(size_t)r0 * DMODEL + col] =
            cvt_f16x2(o[n][0] * inv0, o[n][1] * inv0);
        *(uint32_t*)&OF[(size_t)(r0 + 8) * DMODEL + col] =
            cvt_f16x2(o[n][2] * inv1, o[n][3] * inv1);
    }
}

// ---------------------------------------------------------------------------
extern "C" void kernel_launch(void* const* d_in, const int* in_sizes, int n_in,
                              void* d_out, int out_size)
{
    const float* x  = (const float*)d_in[0];
    const float* Wq = (const float*)d_in[1];
    const float* bq = (const float*)d_in[2];
    const float* Wk = (const float*)d_in[3];
    const float* bk = (const float*)d_in[4];
    const float* Wv = (const float*)d_in[5];
    const float* bv = (const float*)d_in[6];
    const float* Wo = (const float*)d_in[7];
    const float* bo = (const float*)d_in[8];
    float* out = (float*)d_out;

    __half *a16, *wthi, *wtlo, *q16, *k16, *v16;
    cudaGetSymbolAddress((void**)&a16, g_a16);
    cudaGetSymbolAddress((void**)&wthi, g_wthi);
    cudaGetSymbolAddress((void**)&wtlo, g_wtlo);
    cudaGetSymbolAddress((void**)&q16, g_q16);
    cudaGetSymbolAddress((void**)&k16, g_k16);
    cudaGetSymbolAddress((void**)&v16, g_v16);

    cudaFuncSetAttribute(gemm_f16, cudaFuncAttributeMaxDynamicSharedMemorySize, GS_TOTAL);
    cudaFuncSetAttribute(attn_mma, cudaFuncAttributeMaxDynamicSharedMemorySize, AT_SMEM);

    const int WSZ = DMODEL * DMODEL;

    // 1) one launch: x -> fp16 (z=4) + transpose/split 4 weights (z=0..3)
    conv_all<<<dim3(32, 32, 5), 256>>>(x, Wq, Wk, Wv, Wo, a16, wthi, wtlo);

    // 2) persistent fused QKV projection: 256 CTAs x 3 tiles (all single out)
    gemm_f16<<<256, 256, GS_TOTAL>>>(
        a16, wthi, wtlo, bq, bk, bv,
        nullptr, q16, k16, v16, 1, 3);

    // 3) fp16 attention (all-single operands) -> fp16 output into a16
    attn_mma<<<dim3(S_LEN / 128, NHEAD, BATCH), 256, AT_SMEM>>>(
        q16, k16, v16, a16);

    // 4) output projection: 256 CTAs x 1 tile -> fp32 final
    gemm_f16<<<256, 256, GS_TOTAL>>>(
        a16, wthi + 3 * WSZ, wtlo + 3 * WSZ, bo, bo, bo,
        out, nullptr, nullptr, nullptr, 0, 1);
}